// round 15
// baseline (speedup 1.0000x reference)
#include <cuda_runtime.h>
#include <math.h>
#include <stdint.h>

#define Bq   8
#define Tq   2048
#define DINq 512
#define Dq   1024
#define Mq   (Bq*Tq)   // 16384

typedef unsigned long long ull;

// Scratch (static device globals — no runtime allocation).
__device__ float2 g_ab[(size_t)Mq * Dq];     // (a_step, b_step) interleaved
__device__ float  g_xT[(size_t)DINq * Mq];   // x transposed [DIN][M]

// ---------- packed f32x2 helpers ----------
__device__ __forceinline__ ull ffma2(ull a, ull b, ull c) {
    ull d;
    asm("fma.rn.f32x2 %0, %1, %2, %3;" : "=l"(d) : "l"(a), "l"(b), "l"(c));
    return d;
}
__device__ __forceinline__ ull dup2(float x) {
    ull r;
    asm("mov.b64 %0, {%1, %1};" : "=l"(r) : "f"(x));
    return r;
}
__device__ __forceinline__ void upk2(ull r, float& x, float& y) {
    asm("mov.b64 {%0, %1}, %2;" : "=f"(x), "=f"(y) : "l"(r));
}
__device__ __forceinline__ uint32_t smem_u32(const void* p) {
    uint32_t a;
    asm("{ .reg .u64 t; cvta.to.shared.u64 t, %1; cvt.u32.u64 %0, t; }" : "=r"(a) : "l"(p));
    return a;
}
__device__ __forceinline__ void cp16(uint32_t dst, const void* src) {
    asm volatile("cp.async.cg.shared.global [%0], [%1], 16;" :: "r"(dst), "l"(src));
}
__device__ __forceinline__ void cp8(uint32_t dst, const void* src) {
    asm volatile("cp.async.ca.shared.global [%0], [%1], 8;" :: "r"(dst), "l"(src));
}

// ---------- x transpose: [M][DIN] -> [DIN][M] ----------
__global__ __launch_bounds__(256) void transpose_x(const float* __restrict__ x) {
    __shared__ float t[32][33];
    const int k0 = blockIdx.x * 32, m0 = blockIdx.y * 32;
    const int tx = threadIdx.x & 31, ty = threadIdx.x >> 5;   // ty 0..7
#pragma unroll
    for (int r = 0; r < 32; r += 8)
        t[ty + r][tx] = x[(size_t)(m0 + ty + r) * DINq + k0 + tx];
    __syncthreads();
#pragma unroll
    for (int r = 0; r < 32; r += 8)
        g_xT[(size_t)(k0 + ty + r) * Mq + m0 + tx] = t[tx][ty + r];
}

// ---------- fused dual GEMM + discretization epilogue ----------
// CTA tile 128(M) x 64(N), BK=16, 256 threads, thread tile 8x4 per GEMM.
// M-pair f32x2 accumulation: A operands are natural longlong2 smem loads
// (zero movs); W operands dup2'd in registers (8 movs/k). 4-stage cp.async ring.
#define BM 128
#define BN 64
#define BK 16
#define CHUNKS (DINq / BK)   // 32
#define AROW 136             // floats, pad 8 (16B-aligned rows)
#define STAGE_B 16896        // A 16*136*4=8704, Wd 4096, Wb 4096
#define AS_OFF 0
#define WD_OFF 8704
#define WB_OFF 12800
#define GEMM_SMEM (4 * STAGE_B)   // 67584

__device__ __forceinline__ void stage_chunk(
    uint32_t sb, int c, int tid,
    const float* __restrict__ Wd, const float* __restrict__ Wb,
    int m0, int n0)
{
    const uint32_t base = sb + (c & 3) * STAGE_B;
    const int k0 = c * BK;
#pragma unroll
    for (int it = 0; it < 2; it++) {
        const int idx = it * 256 + tid;
        const int k = idx >> 5, c16 = idx & 31;
        cp16(base + AS_OFF + k * (AROW * 4) + c16 * 16,
             g_xT + (size_t)(k0 + k) * Mq + m0 + c16 * 4);
    }
    {
        const int k = tid >> 4, c4 = tid & 15;
        cp16(base + WD_OFF + k * 256 + c4 * 16, Wd + (size_t)(k0 + k) * Dq + n0 + c4 * 4);
        cp16(base + WB_OFF + k * 256 + c4 * 16, Wb + (size_t)(k0 + k) * Dq + n0 + c4 * 4);
    }
    asm volatile("cp.async.commit_group;");
}

__global__ __launch_bounds__(256, 2) void fused_gemm_kernel(
    const float* __restrict__ Wd,  // [DIN, D]
    const float* __restrict__ bd,  // [D]
    const float* __restrict__ Wb,  // [DIN, D]
    const float* __restrict__ bb,  // [D]
    const float* __restrict__ A_log)
{
    extern __shared__ char smem[];
    const uint32_t sb = smem_u32(smem);
    const int tid = threadIdx.x;
    const int tx = tid & 15;       // N direction (4 cols each)
    const int ty = tid >> 4;       // M direction (8 rows = 4 pairs)
    const int n0 = blockIdx.x * BN;
    const int m0 = blockIdx.y * BM;

    // acc[mp][j]: f32x2 over (m = ty*8 + mp*2 {lo}, +1 {hi}), col n0 + tx*4 + j
    ull accd[4][4], accb[4][4];
#pragma unroll
    for (int i = 0; i < 4; i++)
#pragma unroll
        for (int j = 0; j < 4; j++) { accd[i][j] = 0ull; accb[i][j] = 0ull; }

    stage_chunk(sb, 0, tid, Wd, Wb, m0, n0);
    stage_chunk(sb, 1, tid, Wd, Wb, m0, n0);

    for (int c = 0; c < CHUNKS; c++) {
        if (c + 2 < CHUNKS) {
            stage_chunk(sb, c + 2, tid, Wd, Wb, m0, n0);
            asm volatile("cp.async.wait_group 2;");
        } else if (c + 1 < CHUNKS) {
            asm volatile("cp.async.wait_group 1;");
        } else {
            asm volatile("cp.async.wait_group 0;");
        }
        __syncthreads();

        const char* stg = smem + (c & 3) * STAGE_B;
        const float* As  = (const float*)(stg + AS_OFF);
        const float* Wds = (const float*)(stg + WD_OFF);
        const float* Wbs = (const float*)(stg + WB_OFF);
#pragma unroll
        for (int k = 0; k < BK; k++) {
            longlong2 A0 = *(const longlong2*)&As[k * AROW + ty * 8];
            longlong2 A1 = *(const longlong2*)&As[k * AROW + ty * 8 + 4];
            float4 wd4 = *(const float4*)&Wds[k * BN + tx * 4];
            float4 wb4 = *(const float4*)&Wbs[k * BN + tx * 4];
            const ull ap[4] = {(ull)A0.x, (ull)A0.y, (ull)A1.x, (ull)A1.y};
            const ull wdv[4] = {dup2(wd4.x), dup2(wd4.y), dup2(wd4.z), dup2(wd4.w)};
            const ull wbv[4] = {dup2(wb4.x), dup2(wb4.y), dup2(wb4.z), dup2(wb4.w)};
#pragma unroll
            for (int mp = 0; mp < 4; mp++)
#pragma unroll
                for (int j = 0; j < 4; j++) {
                    accd[mp][j] = ffma2(ap[mp], wdv[j], accd[mp][j]);
                    accb[mp][j] = ffma2(ap[mp], wbv[j], accb[mp][j]);
                }
        }
    }

    // epilogue: delta = softplus(xWd+bd); a = exp(-delta*exp(A_log)); b = delta*(xWb+bb)
    float bdv[4], bbv[4], Av[4];
#pragma unroll
    for (int j = 0; j < 4; j++) {
        const int n = n0 + tx * 4 + j;
        bdv[j] = __ldg(&bd[n]);
        bbv[j] = __ldg(&bb[n]);
        Av[j]  = expf(__ldg(&A_log[n]));
    }
#pragma unroll
    for (int mp = 0; mp < 4; mp++) {
        float dlo[4], dhi[4], blo[4], bhi[4];
#pragma unroll
        for (int j = 0; j < 4; j++) {
            upk2(accd[mp][j], dlo[j], dhi[j]);
            upk2(accb[mp][j], blo[j], bhi[j]);
        }
        const int mbase = m0 + ty * 8 + mp * 2;
#pragma unroll
        for (int h = 0; h < 2; h++) {
            const float* dz = h ? dhi : dlo;
            const float* bz = h ? bhi : blo;
            float2 o[4];
#pragma unroll
            for (int j = 0; j < 4; j++) {
                const float z = dz[j] + bdv[j];
                const float delta = (z > 0.f) ? (z + log1pf(expf(-z))) : log1pf(expf(z));
                o[j].x = expf(-delta * Av[j]);
                o[j].y = delta * (bz[j] + bbv[j]);
            }
            float2* dst = &g_ab[(size_t)(mbase + h) * Dq + n0 + tx * 4];
            *(float4*)(dst + 0) = *(const float4*)(o + 0);
            *(float4*)(dst + 2) = *(const float4*)(o + 2);
        }
    }
}

// ---------- sequential spiking scan: cp.async smem ring (round-12 proven) ----------
#define SD 8          // ring depth (batches)
#define SBATCH 8      // timesteps per batch
#define NBATCH (Tq / SBATCH)   // 256

__global__ __launch_bounds__(32) void scan_kernel(
    const float* __restrict__ thr,
    float* __restrict__ h_out, float* __restrict__ s_out)
{
    __shared__ float2 ring[SD][SBATCH][32];
    const int lane = threadIdx.x;
    const int c = blockIdx.x * 32 + lane;          // 0 .. B*D-1
    const int b = c >> 10;
    const int d = c & 1023;
    const size_t base = (size_t)b * Tq * Dq + d;
    const float th = thr[d];
    const float2* src = g_ab + base;
    const uint32_t rb = smem_u32(&ring[0][0][lane]);

    auto issue = [&](int i) {
        const uint32_t slot = rb + (uint32_t)(i & (SD - 1)) * (SBATCH * 32 * 8);
        const float2* s = src + (size_t)i * SBATCH * Dq;
#pragma unroll
        for (int j = 0; j < SBATCH; j++)
            cp8(slot + j * 32 * 8, s + (size_t)j * Dq);
        asm volatile("cp.async.commit_group;");
    };

#pragma unroll
    for (int p = 0; p < SD - 1; p++) issue(p);     // batches 0..6 in flight

    float h = 0.f;
    for (int i = 0; i < NBATCH - (SD - 1); i++) {
        asm volatile("cp.async.wait_group %0;" :: "n"(SD - 2));   // batch i ready
        const float2* bt = &ring[i & (SD - 1)][0][lane];
        const size_t t0 = (size_t)i * SBATCH;
#pragma unroll
        for (int j = 0; j < SBATCH; j++) {
            float2 v = bt[(size_t)j * 32];
            h = fmaf(v.x, h, v.y);
            const bool sp = (h > th);
            const size_t o = base + (t0 + j) * Dq;
            s_out[o] = sp ? 1.f : 0.f;
            h = sp ? 0.f : h;
            h_out[o] = h;
        }
        issue(i + SD - 1);
    }
    asm volatile("cp.async.wait_group 0;");
#pragma unroll
    for (int i = NBATCH - (SD - 1); i < NBATCH; i++) {
        const float2* bt = &ring[i & (SD - 1)][0][lane];
        const size_t t0 = (size_t)i * SBATCH;
#pragma unroll
        for (int j = 0; j < SBATCH; j++) {
            float2 v = bt[(size_t)j * 32];
            h = fmaf(v.x, h, v.y);
            const bool sp = (h > th);
            const size_t o = base + (t0 + j) * Dq;
            s_out[o] = sp ? 1.f : 0.f;
            h = sp ? 0.f : h;
            h_out[o] = h;
        }
    }
}

// ---------- LayerNorm over D (in place on d_out first half) ----------
__global__ __launch_bounds__(256) void ln_kernel(
    const float* __restrict__ gamma, const float* __restrict__ beta,
    float* __restrict__ out)
{
    const int row = blockIdx.x;
    const int tid = threadIdx.x;
    const int lane = tid & 31, wid = tid >> 5;
    size_t off = (size_t)row * Dq + tid * 4;
    float4 v = *(float4*)&out[off];

    __shared__ float ws[8];
    float s = v.x + v.y + v.z + v.w;
#pragma unroll
    for (int o = 16; o > 0; o >>= 1) s += __shfl_xor_sync(0xFFFFFFFFu, s, o);
    if (lane == 0) ws[wid] = s;
    __syncthreads();
    float tot = 0.f;
#pragma unroll
    for (int i = 0; i < 8; i++) tot += ws[i];
    float mu = tot * (1.f / Dq);
    __syncthreads();

    float d0 = v.x - mu, d1 = v.y - mu, d2 = v.z - mu, d3 = v.w - mu;
    float q = d0 * d0 + d1 * d1 + d2 * d2 + d3 * d3;
#pragma unroll
    for (int o = 16; o > 0; o >>= 1) q += __shfl_xor_sync(0xFFFFFFFFu, q, o);
    if (lane == 0) ws[wid] = q;
    __syncthreads();
    float tq = 0.f;
#pragma unroll
    for (int i = 0; i < 8; i++) tq += ws[i];
    float rstd = rsqrtf(tq * (1.f / Dq) + 1e-5f);

    int d = tid * 4;
    float4 g = *(const float4*)&gamma[d];
    float4 be = *(const float4*)&beta[d];
    float4 o;
    o.x = d0 * rstd * g.x + be.x;
    o.y = d1 * rstd * g.y + be.y;
    o.z = d2 * rstd * g.z + be.z;
    o.w = d3 * rstd * g.w + be.w;
    *(float4*)&out[off] = o;
}

extern "C" void kernel_launch(void* const* d_in, const int* in_sizes, int n_in,
                              void* d_out, int out_size)
{
    const float* x     = (const float*)d_in[0];
    const float* Wd    = (const float*)d_in[1];
    const float* bd    = (const float*)d_in[2];
    const float* Wb    = (const float*)d_in[3];
    const float* bb    = (const float*)d_in[4];
    const float* A_log = (const float*)d_in[5];
    const float* thr   = (const float*)d_in[6];
    const float* gamma = (const float*)d_in[7];
    const float* beta  = (const float*)d_in[8];

    float* out    = (float*)d_out;                    // [B,T,D] normalized output
    float* spikes = out + (size_t)Mq * Dq;            // [B,T,D] spikes

    cudaFuncSetAttribute(fused_gemm_kernel,
                         cudaFuncAttributeMaxDynamicSharedMemorySize, GEMM_SMEM);

    transpose_x<<<dim3(DINq / 32, Mq / 32), 256>>>(x);
    fused_gemm_kernel<<<dim3(Dq / BN, Mq / BM), 256, GEMM_SMEM>>>(Wd, bd, Wb, bb, A_log);
    scan_kernel<<<(Bq * Dq) / 32, 32>>>(thr, out, spikes);
    ln_kernel<<<Mq, 256>>>(gamma, beta, out);
}

// round 16
// speedup vs baseline: 1.0486x; 1.0486x over previous
#include <cuda_runtime.h>
#include <math.h>
#include <stdint.h>

#define Bq   8
#define Tq   2048
#define DINq 512
#define Dq   1024
#define Mq   (Bq*Tq)   // 16384

typedef unsigned long long ull;

// Scratch (static device globals — no runtime allocation).
__device__ float2 g_ab[(size_t)Mq * Dq];     // (a_step, b_step) interleaved
__device__ float  g_xT[(size_t)DINq * Mq];   // x transposed [DIN][M]

// ---------- packed f32x2 helpers ----------
__device__ __forceinline__ ull ffma2(ull a, ull b, ull c) {
    ull d;
    asm("fma.rn.f32x2 %0, %1, %2, %3;" : "=l"(d) : "l"(a), "l"(b), "l"(c));
    return d;
}
__device__ __forceinline__ ull pk2(float x, float y) {
    ull r;
    asm("mov.b64 %0, {%1, %2};" : "=l"(r) : "f"(x), "f"(y));
    return r;
}
__device__ __forceinline__ ull dup2(float x) {
    ull r;
    asm("mov.b64 %0, {%1, %1};" : "=l"(r) : "f"(x));
    return r;
}
__device__ __forceinline__ void upk2(ull r, float& x, float& y) {
    asm("mov.b64 {%0, %1}, %2;" : "=f"(x), "=f"(y) : "l"(r));
}
__device__ __forceinline__ uint32_t smem_u32(const void* p) {
    uint32_t a;
    asm("{ .reg .u64 t; cvta.to.shared.u64 t, %1; cvt.u32.u64 %0, t; }" : "=r"(a) : "l"(p));
    return a;
}
__device__ __forceinline__ void cp16(uint32_t dst, const void* src) {
    asm volatile("cp.async.cg.shared.global [%0], [%1], 16;" :: "r"(dst), "l"(src));
}
__device__ __forceinline__ void cp8(uint32_t dst, const void* src) {
    asm volatile("cp.async.ca.shared.global [%0], [%1], 8;" :: "r"(dst), "l"(src));
}

// ---------- x transpose: [M][DIN] -> [DIN][M] ----------
__global__ __launch_bounds__(256) void transpose_x(const float* __restrict__ x) {
    __shared__ float t[32][33];
    const int k0 = blockIdx.x * 32, m0 = blockIdx.y * 32;
    const int tx = threadIdx.x & 31, ty = threadIdx.x >> 5;   // ty 0..7
#pragma unroll
    for (int r = 0; r < 32; r += 8)
        t[ty + r][tx] = x[(size_t)(m0 + ty + r) * DINq + k0 + tx];
    __syncthreads();
#pragma unroll
    for (int r = 0; r < 32; r += 8)
        g_xT[(size_t)(k0 + ty + r) * Mq + m0 + tx] = t[tx][ty + r];
}

// ---------- fused dual GEMM + discretization epilogue (round-12 frozen) ----------
#define BM 128
#define BN 64
#define BK 16
#define CHUNKS (DINq / BK)   // 32
#define AROW 136             // floats, pad 8 (16B-aligned rows)
#define STAGE_B 16896        // A 16*136*4=8704, Wd 4096, Wb 4096
#define AS_OFF 0
#define WD_OFF 8704
#define WB_OFF 12800
#define GEMM_SMEM (4 * STAGE_B)   // 67584

__device__ __forceinline__ void stage_chunk(
    uint32_t sb, int c, int tid,
    const float* __restrict__ Wd, const float* __restrict__ Wb,
    int m0, int n0)
{
    const uint32_t base = sb + (c & 3) * STAGE_B;
    const int k0 = c * BK;
#pragma unroll
    for (int it = 0; it < 2; it++) {
        const int idx = it * 256 + tid;
        const int k = idx >> 5, c16 = idx & 31;
        cp16(base + AS_OFF + k * (AROW * 4) + c16 * 16,
             g_xT + (size_t)(k0 + k) * Mq + m0 + c16 * 4);
    }
    {
        const int k = tid >> 4, c4 = tid & 15;
        cp16(base + WD_OFF + k * 256 + c4 * 16, Wd + (size_t)(k0 + k) * Dq + n0 + c4 * 4);
        cp16(base + WB_OFF + k * 256 + c4 * 16, Wb + (size_t)(k0 + k) * Dq + n0 + c4 * 4);
    }
    asm volatile("cp.async.commit_group;");
}

__global__ __launch_bounds__(256, 2) void fused_gemm_kernel(
    const float* __restrict__ Wd,  // [DIN, D]
    const float* __restrict__ bd,  // [D]
    const float* __restrict__ Wb,  // [DIN, D]
    const float* __restrict__ bb,  // [D]
    const float* __restrict__ A_log)
{
    extern __shared__ char smem[];
    const uint32_t sb = smem_u32(smem);
    const int tid = threadIdx.x;
    const int tx = tid & 15;       // N direction (4 cols each)
    const int ty = tid >> 4;       // M direction (8 rows each)
    const int n0 = blockIdx.x * BN;
    const int m0 = blockIdx.y * BM;

    ull accd[8][2], accb[8][2];
#pragma unroll
    for (int i = 0; i < 8; i++) {
        accd[i][0] = 0ull; accd[i][1] = 0ull;
        accb[i][0] = 0ull; accb[i][1] = 0ull;
    }

    stage_chunk(sb, 0, tid, Wd, Wb, m0, n0);
    stage_chunk(sb, 1, tid, Wd, Wb, m0, n0);

    for (int c = 0; c < CHUNKS; c++) {
        if (c + 2 < CHUNKS) {
            stage_chunk(sb, c + 2, tid, Wd, Wb, m0, n0);
            asm volatile("cp.async.wait_group 2;");
        } else if (c + 1 < CHUNKS) {
            asm volatile("cp.async.wait_group 1;");
        } else {
            asm volatile("cp.async.wait_group 0;");
        }
        __syncthreads();

        const char* stg = smem + (c & 3) * STAGE_B;
        const float* As  = (const float*)(stg + AS_OFF);
        const float* Wds = (const float*)(stg + WD_OFF);
        const float* Wbs = (const float*)(stg + WB_OFF);
#pragma unroll
        for (int k = 0; k < BK; k++) {
            float4 a0 = *(const float4*)&As[k * AROW + ty * 8];
            float4 a1 = *(const float4*)&As[k * AROW + ty * 8 + 4];
            float4 wd4 = *(const float4*)&Wds[k * BN + tx * 4];
            float4 wb4 = *(const float4*)&Wbs[k * BN + tx * 4];
            ull d0 = pk2(wd4.x, wd4.y), d1 = pk2(wd4.z, wd4.w);
            ull b0 = pk2(wb4.x, wb4.y), b1 = pk2(wb4.z, wb4.w);
            float am[8] = {a0.x, a0.y, a0.z, a0.w, a1.x, a1.y, a1.z, a1.w};
#pragma unroll
            for (int i = 0; i < 8; i++) {
                ull a2 = dup2(am[i]);
                accd[i][0] = ffma2(a2, d0, accd[i][0]);
                accd[i][1] = ffma2(a2, d1, accd[i][1]);
                accb[i][0] = ffma2(a2, b0, accb[i][0]);
                accb[i][1] = ffma2(a2, b1, accb[i][1]);
            }
        }
    }

    // epilogue: delta = softplus(xWd+bd); a = exp(-delta*exp(A_log)); b = delta*(xWb+bb)
    float bdv[4], bbv[4], Av[4];
#pragma unroll
    for (int j = 0; j < 4; j++) {
        const int n = n0 + tx * 4 + j;
        bdv[j] = __ldg(&bd[n]);
        bbv[j] = __ldg(&bb[n]);
        Av[j]  = expf(__ldg(&A_log[n]));
    }
#pragma unroll
    for (int i = 0; i < 8; i++) {
        const int m = m0 + ty * 8 + i;
        float dd[4], bo[4];
        upk2(accd[i][0], dd[0], dd[1]); upk2(accd[i][1], dd[2], dd[3]);
        upk2(accb[i][0], bo[0], bo[1]); upk2(accb[i][1], bo[2], bo[3]);
        float2 o[4];
#pragma unroll
        for (int j = 0; j < 4; j++) {
            const float z = dd[j] + bdv[j];
            const float delta = (z > 0.f) ? (z + log1pf(expf(-z))) : log1pf(expf(z));
            o[j].x = expf(-delta * Av[j]);
            o[j].y = delta * (bo[j] + bbv[j]);
        }
        float2* dst = &g_ab[(size_t)m * Dq + n0 + tx * 4];
        *(float4*)(dst + 0) = *(const float4*)(o + 0);
        *(float4*)(dst + 2) = *(const float4*)(o + 2);
    }
}

// ---------- sequential spiking scan: cp.async smem ring (round-12 frozen) ----------
#define SD 8          // ring depth (batches)
#define SBATCH 8      // timesteps per batch
#define NBATCH (Tq / SBATCH)   // 256

__global__ __launch_bounds__(32) void scan_kernel(
    const float* __restrict__ thr,
    float* __restrict__ h_out, float* __restrict__ s_out)
{
    __shared__ float2 ring[SD][SBATCH][32];
    const int lane = threadIdx.x;
    const int c = blockIdx.x * 32 + lane;          // 0 .. B*D-1
    const int b = c >> 10;
    const int d = c & 1023;
    const size_t base = (size_t)b * Tq * Dq + d;
    const float th = thr[d];
    const float2* src = g_ab + base;
    const uint32_t rb = smem_u32(&ring[0][0][lane]);

    auto issue = [&](int i) {
        const uint32_t slot = rb + (uint32_t)(i & (SD - 1)) * (SBATCH * 32 * 8);
        const float2* s = src + (size_t)i * SBATCH * Dq;
#pragma unroll
        for (int j = 0; j < SBATCH; j++)
            cp8(slot + j * 32 * 8, s + (size_t)j * Dq);
        asm volatile("cp.async.commit_group;");
    };

#pragma unroll
    for (int p = 0; p < SD - 1; p++) issue(p);     // batches 0..6 in flight

    float h = 0.f;
    for (int i = 0; i < NBATCH - (SD - 1); i++) {
        asm volatile("cp.async.wait_group %0;" :: "n"(SD - 2));   // batch i ready
        const float2* bt = &ring[i & (SD - 1)][0][lane];
        const size_t t0 = (size_t)i * SBATCH;
#pragma unroll
        for (int j = 0; j < SBATCH; j++) {
            float2 v = bt[(size_t)j * 32];
            h = fmaf(v.x, h, v.y);
            const bool sp = (h > th);
            const size_t o = base + (t0 + j) * Dq;
            s_out[o] = sp ? 1.f : 0.f;
            h = sp ? 0.f : h;
            h_out[o] = h;
        }
        issue(i + SD - 1);
    }
    asm volatile("cp.async.wait_group 0;");
#pragma unroll
    for (int i = NBATCH - (SD - 1); i < NBATCH; i++) {
        const float2* bt = &ring[i & (SD - 1)][0][lane];
        const size_t t0 = (size_t)i * SBATCH;
#pragma unroll
        for (int j = 0; j < SBATCH; j++) {
            float2 v = bt[(size_t)j * 32];
            h = fmaf(v.x, h, v.y);
            const bool sp = (h > th);
            const size_t o = base + (t0 + j) * Dq;
            s_out[o] = sp ? 1.f : 0.f;
            h = sp ? 0.f : h;
            h_out[o] = h;
        }
    }
}

// ---------- LayerNorm: warp-per-row, barrier-free (8 rows/CTA) ----------
__global__ __launch_bounds__(256) void ln_kernel(
    const float* __restrict__ gamma, const float* __restrict__ beta,
    float* __restrict__ out)
{
    const int wid = threadIdx.x >> 5, lane = threadIdx.x & 31;
    const int row = blockIdx.x * 8 + wid;
    float* rp = out + (size_t)row * Dq;

    // lane holds 8 float4s: elements lane*4 + j*128 (coalesced 128B per j)
    float4 v[8];
#pragma unroll
    for (int j = 0; j < 8; j++)
        v[j] = *(const float4*)(rp + j * 128 + lane * 4);

    float s = 0.f;
#pragma unroll
    for (int j = 0; j < 8; j++) s += (v[j].x + v[j].y) + (v[j].z + v[j].w);
#pragma unroll
    for (int o = 16; o > 0; o >>= 1) s += __shfl_xor_sync(0xFFFFFFFFu, s, o);
    const float mu = s * (1.f / Dq);

    float q = 0.f;
#pragma unroll
    for (int j = 0; j < 8; j++) {
        float d0 = v[j].x - mu, d1 = v[j].y - mu, d2 = v[j].z - mu, d3 = v[j].w - mu;
        q += d0 * d0 + d1 * d1 + d2 * d2 + d3 * d3;
    }
#pragma unroll
    for (int o = 16; o > 0; o >>= 1) q += __shfl_xor_sync(0xFFFFFFFFu, q, o);
    const float rstd = rsqrtf(q * (1.f / Dq) + 1e-5f);

#pragma unroll
    for (int j = 0; j < 8; j++) {
        const int d = j * 128 + lane * 4;
        float4 g  = *(const float4*)(gamma + d);
        float4 be = *(const float4*)(beta + d);
        float4 o;
        o.x = (v[j].x - mu) * rstd * g.x + be.x;
        o.y = (v[j].y - mu) * rstd * g.y + be.y;
        o.z = (v[j].z - mu) * rstd * g.z + be.z;
        o.w = (v[j].w - mu) * rstd * g.w + be.w;
        *(float4*)(rp + d) = o;
    }
}

extern "C" void kernel_launch(void* const* d_in, const int* in_sizes, int n_in,
                              void* d_out, int out_size)
{
    const float* x     = (const float*)d_in[0];
    const float* Wd    = (const float*)d_in[1];
    const float* bd    = (const float*)d_in[2];
    const float* Wb    = (const float*)d_in[3];
    const float* bb    = (const float*)d_in[4];
    const float* A_log = (const float*)d_in[5];
    const float* thr   = (const float*)d_in[6];
    const float* gamma = (const float*)d_in[7];
    const float* beta  = (const float*)d_in[8];

    float* out    = (float*)d_out;                    // [B,T,D] normalized output
    float* spikes = out + (size_t)Mq * Dq;            // [B,T,D] spikes

    cudaFuncSetAttribute(fused_gemm_kernel,
                         cudaFuncAttributeMaxDynamicSharedMemorySize, GEMM_SMEM);

    transpose_x<<<dim3(DINq / 32, Mq / 32), 256>>>(x);
    fused_gemm_kernel<<<dim3(Dq / BN, Mq / BM), 256, GEMM_SMEM>>>(Wd, bd, Wb, bb, A_log);
    scan_kernel<<<(Bq * Dq) / 32, 32>>>(thr, out, spikes);
    ln_kernel<<<Mq / 8, 256>>>(gamma, beta, out);
}

// round 17
// speedup vs baseline: 1.0499x; 1.0012x over previous
#include <cuda_runtime.h>
#include <math.h>
#include <stdint.h>

#define Bq   8
#define Tq   2048
#define DINq 512
#define Dq   1024
#define Mq   (Bq*Tq)   // 16384

typedef unsigned long long ull;

// Scratch (static device globals — no runtime allocation).
__device__ float2 g_ab[(size_t)Mq * Dq];     // (a_step, b_step) interleaved
__device__ float  g_xT[(size_t)DINq * Mq];   // x transposed [DIN][M]

// ---------- packed f32x2 helpers ----------
__device__ __forceinline__ ull ffma2(ull a, ull b, ull c) {
    ull d;
    asm("fma.rn.f32x2 %0, %1, %2, %3;" : "=l"(d) : "l"(a), "l"(b), "l"(c));
    return d;
}
__device__ __forceinline__ ull pk2(float x, float y) {
    ull r;
    asm("mov.b64 %0, {%1, %2};" : "=l"(r) : "f"(x), "f"(y));
    return r;
}
__device__ __forceinline__ ull dup2(float x) {
    ull r;
    asm("mov.b64 %0, {%1, %1};" : "=l"(r) : "f"(x));
    return r;
}
__device__ __forceinline__ void upk2(ull r, float& x, float& y) {
    asm("mov.b64 {%0, %1}, %2;" : "=f"(x), "=f"(y) : "l"(r));
}
__device__ __forceinline__ uint32_t smem_u32(const void* p) {
    uint32_t a;
    asm("{ .reg .u64 t; cvta.to.shared.u64 t, %1; cvt.u32.u64 %0, t; }" : "=r"(a) : "l"(p));
    return a;
}
__device__ __forceinline__ void cp16(uint32_t dst, const void* src) {
    asm volatile("cp.async.cg.shared.global [%0], [%1], 16;" :: "r"(dst), "l"(src));
}
__device__ __forceinline__ void cp8(uint32_t dst, const void* src) {
    asm volatile("cp.async.ca.shared.global [%0], [%1], 8;" :: "r"(dst), "l"(src));
}

// ---------- x transpose: [M][DIN] -> [DIN][M] ----------
__global__ __launch_bounds__(256) void transpose_x(const float* __restrict__ x) {
    __shared__ float t[32][33];
    const int k0 = blockIdx.x * 32, m0 = blockIdx.y * 32;
    const int tx = threadIdx.x & 31, ty = threadIdx.x >> 5;   // ty 0..7
#pragma unroll
    for (int r = 0; r < 32; r += 8)
        t[ty + r][tx] = x[(size_t)(m0 + ty + r) * DINq + k0 + tx];
    __syncthreads();
#pragma unroll
    for (int r = 0; r < 32; r += 8)
        g_xT[(size_t)(k0 + ty + r) * Mq + m0 + tx] = t[tx][ty + r];
}

// ---------- fused dual GEMM + discretization epilogue (round-12 frozen) ----------
#define BM 128
#define BN 64
#define BK 16
#define CHUNKS (DINq / BK)   // 32
#define AROW 136             // floats, pad 8 (16B-aligned rows)
#define STAGE_B 16896        // A 16*136*4=8704, Wd 4096, Wb 4096
#define AS_OFF 0
#define WD_OFF 8704
#define WB_OFF 12800
#define GEMM_SMEM (4 * STAGE_B)   // 67584

__device__ __forceinline__ void stage_chunk(
    uint32_t sb, int c, int tid,
    const float* __restrict__ Wd, const float* __restrict__ Wb,
    int m0, int n0)
{
    const uint32_t base = sb + (c & 3) * STAGE_B;
    const int k0 = c * BK;
#pragma unroll
    for (int it = 0; it < 2; it++) {
        const int idx = it * 256 + tid;
        const int k = idx >> 5, c16 = idx & 31;
        cp16(base + AS_OFF + k * (AROW * 4) + c16 * 16,
             g_xT + (size_t)(k0 + k) * Mq + m0 + c16 * 4);
    }
    {
        const int k = tid >> 4, c4 = tid & 15;
        cp16(base + WD_OFF + k * 256 + c4 * 16, Wd + (size_t)(k0 + k) * Dq + n0 + c4 * 4);
        cp16(base + WB_OFF + k * 256 + c4 * 16, Wb + (size_t)(k0 + k) * Dq + n0 + c4 * 4);
    }
    asm volatile("cp.async.commit_group;");
}

__global__ __launch_bounds__(256, 2) void fused_gemm_kernel(
    const float* __restrict__ Wd,  // [DIN, D]
    const float* __restrict__ bd,  // [D]
    const float* __restrict__ Wb,  // [DIN, D]
    const float* __restrict__ bb,  // [D]
    const float* __restrict__ A_log)
{
    extern __shared__ char smem[];
    const uint32_t sb = smem_u32(smem);
    const int tid = threadIdx.x;
    const int tx = tid & 15;       // N direction (4 cols each)
    const int ty = tid >> 4;       // M direction (8 rows each)
    const int n0 = blockIdx.x * BN;
    const int m0 = blockIdx.y * BM;

    ull accd[8][2], accb[8][2];
#pragma unroll
    for (int i = 0; i < 8; i++) {
        accd[i][0] = 0ull; accd[i][1] = 0ull;
        accb[i][0] = 0ull; accb[i][1] = 0ull;
    }

    stage_chunk(sb, 0, tid, Wd, Wb, m0, n0);
    stage_chunk(sb, 1, tid, Wd, Wb, m0, n0);

    for (int c = 0; c < CHUNKS; c++) {
        if (c + 2 < CHUNKS) {
            stage_chunk(sb, c + 2, tid, Wd, Wb, m0, n0);
            asm volatile("cp.async.wait_group 2;");
        } else if (c + 1 < CHUNKS) {
            asm volatile("cp.async.wait_group 1;");
        } else {
            asm volatile("cp.async.wait_group 0;");
        }
        __syncthreads();

        const char* stg = smem + (c & 3) * STAGE_B;
        const float* As  = (const float*)(stg + AS_OFF);
        const float* Wds = (const float*)(stg + WD_OFF);
        const float* Wbs = (const float*)(stg + WB_OFF);
#pragma unroll
        for (int k = 0; k < BK; k++) {
            float4 a0 = *(const float4*)&As[k * AROW + ty * 8];
            float4 a1 = *(const float4*)&As[k * AROW + ty * 8 + 4];
            float4 wd4 = *(const float4*)&Wds[k * BN + tx * 4];
            float4 wb4 = *(const float4*)&Wbs[k * BN + tx * 4];
            ull d0 = pk2(wd4.x, wd4.y), d1 = pk2(wd4.z, wd4.w);
            ull b0 = pk2(wb4.x, wb4.y), b1 = pk2(wb4.z, wb4.w);
            float am[8] = {a0.x, a0.y, a0.z, a0.w, a1.x, a1.y, a1.z, a1.w};
#pragma unroll
            for (int i = 0; i < 8; i++) {
                ull a2 = dup2(am[i]);
                accd[i][0] = ffma2(a2, d0, accd[i][0]);
                accd[i][1] = ffma2(a2, d1, accd[i][1]);
                accb[i][0] = ffma2(a2, b0, accb[i][0]);
                accb[i][1] = ffma2(a2, b1, accb[i][1]);
            }
        }
    }

    // epilogue: delta = softplus(xWd+bd); a = exp(-delta*exp(A_log)); b = delta*(xWb+bb)
    float bdv[4], bbv[4], Av[4];
#pragma unroll
    for (int j = 0; j < 4; j++) {
        const int n = n0 + tx * 4 + j;
        bdv[j] = __ldg(&bd[n]);
        bbv[j] = __ldg(&bb[n]);
        Av[j]  = expf(__ldg(&A_log[n]));
    }
#pragma unroll
    for (int i = 0; i < 8; i++) {
        const int m = m0 + ty * 8 + i;
        float dd[4], bo[4];
        upk2(accd[i][0], dd[0], dd[1]); upk2(accd[i][1], dd[2], dd[3]);
        upk2(accb[i][0], bo[0], bo[1]); upk2(accb[i][1], bo[2], bo[3]);
        float2 o[4];
#pragma unroll
        for (int j = 0; j < 4; j++) {
            const float z = dd[j] + bdv[j];
            const float delta = (z > 0.f) ? (z + log1pf(expf(-z))) : log1pf(expf(z));
            o[j].x = expf(-delta * Av[j]);
            o[j].y = delta * (bo[j] + bbv[j]);
        }
        float2* dst = &g_ab[(size_t)m * Dq + n0 + tx * 4];
        *(float4*)(dst + 0) = *(const float4*)(o + 0);
        *(float4*)(dst + 2) = *(const float4*)(o + 2);
    }
}

// ---------- sequential spiking scan: cp.async smem ring ----------
// 32 threads/CTA, each owns one channel. Ring: 4 batches x 16 steps x 32 lanes x 8B
// = 16 KB. Issue-before-wait (per-lane slots are private, so slot (i+3)%4 ==
// (i-1)%4 was consumed by this thread last iteration). 128 commit/wait pairs.
#define SD 4           // ring depth (batches)
#define SBATCH 16      // timesteps per batch
#define NBATCH (Tq / SBATCH)   // 128

__global__ __launch_bounds__(32) void scan_kernel(
    const float* __restrict__ thr,
    float* __restrict__ h_out, float* __restrict__ s_out)
{
    __shared__ float2 ring[SD][SBATCH][32];
    const int lane = threadIdx.x;
    const int c = blockIdx.x * 32 + lane;          // 0 .. B*D-1
    const int b = c >> 10;
    const int d = c & 1023;
    const size_t base = (size_t)b * Tq * Dq + d;
    const float th = thr[d];
    const float2* src = g_ab + base;
    const uint32_t rb = smem_u32(&ring[0][0][lane]);

    auto issue = [&](int i) {
        const uint32_t slot = rb + (uint32_t)(i & (SD - 1)) * (SBATCH * 32 * 8);
        const float2* s = src + (size_t)i * SBATCH * Dq;
#pragma unroll
        for (int j = 0; j < SBATCH; j++)
            cp8(slot + j * 32 * 8, s + (size_t)j * Dq);
        asm volatile("cp.async.commit_group;");
    };

#pragma unroll
    for (int p = 0; p < SD - 1; p++) issue(p);     // batches 0..2 in flight

    float h = 0.f;
    for (int i = 0; i < NBATCH - (SD - 1); i++) {
        issue(i + SD - 1);                               // overlaps the wait below
        asm volatile("cp.async.wait_group %0;" :: "n"(SD - 1));   // batch i ready
        const float2* bt = &ring[i & (SD - 1)][0][lane];
        const size_t t0 = (size_t)i * SBATCH;
#pragma unroll
        for (int j = 0; j < SBATCH; j++) {
            float2 v = bt[(size_t)j * 32];
            h = fmaf(v.x, h, v.y);
            const bool sp = (h > th);
            const size_t o = base + (t0 + j) * Dq;
            s_out[o] = sp ? 1.f : 0.f;
            h = sp ? 0.f : h;
            h_out[o] = h;
        }
    }
    asm volatile("cp.async.wait_group 0;");
#pragma unroll
    for (int i = NBATCH - (SD - 1); i < NBATCH; i++) {
        const float2* bt = &ring[i & (SD - 1)][0][lane];
        const size_t t0 = (size_t)i * SBATCH;
#pragma unroll
        for (int j = 0; j < SBATCH; j++) {
            float2 v = bt[(size_t)j * 32];
            h = fmaf(v.x, h, v.y);
            const bool sp = (h > th);
            const size_t o = base + (t0 + j) * Dq;
            s_out[o] = sp ? 1.f : 0.f;
            h = sp ? 0.f : h;
            h_out[o] = h;
        }
    }
}

// ---------- LayerNorm: warp-per-row, barrier-free (round-16 frozen) ----------
__global__ __launch_bounds__(256) void ln_kernel(
    const float* __restrict__ gamma, const float* __restrict__ beta,
    float* __restrict__ out)
{
    const int wid = threadIdx.x >> 5, lane = threadIdx.x & 31;
    const int row = blockIdx.x * 8 + wid;
    float* rp = out + (size_t)row * Dq;

    float4 v[8];
#pragma unroll
    for (int j = 0; j < 8; j++)
        v[j] = *(const float4*)(rp + j * 128 + lane * 4);

    float s = 0.f;
#pragma unroll
    for (int j = 0; j < 8; j++) s += (v[j].x + v[j].y) + (v[j].z + v[j].w);
#pragma unroll
    for (int o = 16; o > 0; o >>= 1) s += __shfl_xor_sync(0xFFFFFFFFu, s, o);
    const float mu = s * (1.f / Dq);

    float q = 0.f;
#pragma unroll
    for (int j = 0; j < 8; j++) {
        float d0 = v[j].x - mu, d1 = v[j].y - mu, d2 = v[j].z - mu, d3 = v[j].w - mu;
        q += d0 * d0 + d1 * d1 + d2 * d2 + d3 * d3;
    }
#pragma unroll
    for (int o = 16; o > 0; o >>= 1) q += __shfl_xor_sync(0xFFFFFFFFu, q, o);
    const float rstd = rsqrtf(q * (1.f / Dq) + 1e-5f);

#pragma unroll
    for (int j = 0; j < 8; j++) {
        const int d = j * 128 + lane * 4;
        float4 g  = *(const float4*)(gamma + d);
        float4 be = *(const float4*)(beta + d);
        float4 o;
        o.x = (v[j].x - mu) * rstd * g.x + be.x;
        o.y = (v[j].y - mu) * rstd * g.y + be.y;
        o.z = (v[j].z - mu) * rstd * g.z + be.z;
        o.w = (v[j].w - mu) * rstd * g.w + be.w;
        *(float4*)(rp + d) = o;
    }
}

extern "C" void kernel_launch(void* const* d_in, const int* in_sizes, int n_in,
                              void* d_out, int out_size)
{
    const float* x     = (const float*)d_in[0];
    const float* Wd    = (const float*)d_in[1];
    const float* bd    = (const float*)d_in[2];
    const float* Wb    = (const float*)d_in[3];
    const float* bb    = (const float*)d_in[4];
    const float* A_log = (const float*)d_in[5];
    const float* thr   = (const float*)d_in[6];
    const float* gamma = (const float*)d_in[7];
    const float* beta  = (const float*)d_in[8];

    float* out    = (float*)d_out;                    // [B,T,D] normalized output
    float* spikes = out + (size_t)Mq * Dq;            // [B,T,D] spikes

    cudaFuncSetAttribute(fused_gemm_kernel,
                         cudaFuncAttributeMaxDynamicSharedMemorySize, GEMM_SMEM);

    transpose_x<<<dim3(DINq / 32, Mq / 32), 256>>>(x);
    fused_gemm_kernel<<<dim3(Dq / BN, Mq / BM), 256, GEMM_SMEM>>>(Wd, bd, Wb, bb, A_log);
    scan_kernel<<<(Bq * Dq) / 32, 32>>>(thr, out, spikes);
    ln_kernel<<<Mq / 8, 256>>>(gamma, beta, out);
}